// round 15
// baseline (speedup 1.0000x reference)
#include <cuda_runtime.h>
#include <cuda_bf16.h>
#include <cstdint>

#define N_CELLS 600
#define HW      4096
#define NBF     100
#define MC      20
#define EDGES   21
#define NB      500
#define NB_INIT 100
#define BATCH   32
#define NSTEPS  400
#define ROW     (N_CELLS*BATCH)   /* 19200 */

#define CPC     5
#define WPC     4                  /* 1 sequencer + 3 folders per cell */
#define TPB     (CPC*WPC*32)       /* 640 */
#define NCTA    (N_CELLS/CPC)      /* 120 CTAs = 1/SM uniform */
#define NEARP   10                 /* sequencer ring: 20 slots = 10 u64 pairs */
#define NV      49                 /* chunk barriers v=0..48 (at bodies 9,19,...,489) */
#define WF_Q    43                 /* packed far-weight pairs per (par,e): 14+17+12 */

// dynamic smem layout (bytes)
#define OFF_WN2   0                /* u64 [CPC][21][10]      =  8400  near weights  */
#define OFF_WF2   8400             /* u64 [CPC][2][21][43]   = 72240  far weights   */
#define OFF_WHP   80640            /* f32 [CPC][21] pad      ->  448  head tap d=1  */
#define OFF_SRC   81088            /* int [CPC][21] pad      ->  448  src*BATCH     */
#define OFF_STV   81536            /* f32 [CPC][400]         =  8000  stim conv     */
#define OFF_FACC  89536            /* u64 [2][CPC][3][5][32] = 38400  fold exports  */
#define OFF_SCR   127936           /* f32 [CPC][3][21][32]   = 40320  folder gather */
#define SMEM_DYN  168256

#define FACC(buf,lc,f,q) (((((buf)*CPC+(lc))*3+(f))*5+(q))*32)

// ---------------- scratch (no device allocations). +1 pad row for tail prefetch ----
__device__ float g_spk [(NB+1) * N_CELLS * BATCH];  // [t][c][b], canary -1 until written
__device__ float g_gens[NSTEPS * N_CELLS * BATCH];  // [t'][c][b]
__device__ float g_stimT[HW * BATCH];               // [hw][b]
__device__ float g_sapp [N_CELLS * BATCH];          // [c][b]

// ---------------- helpers ----------------
__device__ __forceinline__ float ldg_relaxed(const float* p) {
    float v;
    asm volatile("ld.relaxed.gpu.global.f32 %0, [%1];" : "=f"(v) : "l"(p));
    return v;
}
__device__ __forceinline__ void stg_relaxed(float* p, float v) {
    asm volatile("st.relaxed.gpu.global.f32 [%0], %1;" :: "l"(p), "f"(v) : "memory");
}
__device__ __forceinline__ unsigned long long pk2(float lo, float hi) {
    unsigned long long u;
    asm("mov.b64 %0, {%1, %2};" : "=l"(u) : "f"(lo), "f"(hi));
    return u;
}
__device__ __forceinline__ float lo2(unsigned long long u) {
    float a, b; asm("mov.b64 {%0, %1}, %2;" : "=f"(a), "=f"(b) : "l"(u)); return a;
}
__device__ __forceinline__ float hi2(unsigned long long u) {
    float a, b; asm("mov.b64 {%0, %1}, %2;" : "=f"(a), "=f"(b) : "l"(u)); return b;
}
__device__ __forceinline__ void fma2(unsigned long long& acc, unsigned long long w, unsigned long long s) {
    asm("fma.rn.f32x2 %0, %1, %2, %0;" : "+l"(acc) : "l"(w), "l"(s));
}
__device__ __forceinline__ void cellbar(int id) {
    asm volatile("bar.sync %0, %1;" :: "r"(id), "r"(WPC*32) : "memory");
}

// ---------------- setup kernels ----------------
__global__ void k_stimT(const float* __restrict__ stim) {
    int b = blockIdx.x;
    for (int i = threadIdx.x; i < HW; i += blockDim.x)
        g_stimT[i*BATCH + b] = stim[(size_t)b*HW + i];
}

__global__ void k_sapp(const float* __restrict__ spat) {
    __shared__ float red[128];
    int c = blockIdx.x, tid = threadIdx.x;
    int g = tid >> 5, b = tid & 31;
    float acc = 0.f;
    const float* sp = spat + (size_t)c*HW;
    #pragma unroll 8
    for (int m = 0; m < HW/4; m++) {
        int i = g + 4*m;
        acc += sp[i] * g_stimT[i*BATCH + b];
    }
    red[tid] = acc;
    __syncthreads();
    if (tid < 32)
        g_sapp[c*BATCH + tid] = red[tid] + red[tid+32] + red[tid+64] + red[tid+96];
}

__global__ void k_init(const float* __restrict__ init) {
    int idx = blockIdx.x*blockDim.x + threadIdx.x;
    if (idx >= NB*ROW) return;
    int tau = idx / ROW, r = idx % ROW;
    int cc = r / BATCH, b = r % BATCH;
    g_spk[idx] = (tau < NB_INIT) ? init[((size_t)b*N_CELLS + cc)*NB_INIT + tau] : -1.0f;
}

// ---------------- folder: folds 10 rows per interval into private ring ----------
// NT taps starting at d0 (d0 implied by QOFF/weights); L = row lag; NP ring pairs;
// NP2 packed weight pairs per edge; F = folder index 0..2.
template<int NT, int L, int NP, int NP2, int QOFF, int F>
__device__ __forceinline__ void run_folder(
    const unsigned long long* __restrict__ wf2cell,  // + lc base
    const int* __restrict__ ssrc_c,
    unsigned long long* __restrict__ facc,
    float* __restrict__ scr,                          // [EDGES][32] scratch for this warp
    int lc, int lane, int barid)
{
    unsigned long long ring[NP];
    #pragma unroll
    for (int p = 0; p < NP; p++) ring[p] = 0ull;

    #pragma unroll 1
    for (int v = 0; v < NV; v++) {
        #pragma unroll
        for (int m = 0; m < 10; m++) {
            const int r_ = 10*v - L + m;
            if (r_ >= 0) {
                const float* rowp = g_spk + (size_t)r_*ROW;
                float sv[EDGES];
                #pragma unroll
                for (int e = 0; e < EDGES; e++) sv[e] = ldg_relaxed(rowp + ssrc_c[e] + lane);
                if (r_ >= NB_INIT) {
                    float mn = sv[0];
                    #pragma unroll
                    for (int e = 1; e < EDGES; e++) mn = fminf(mn, sv[e]);
                    int guard = 0;
                    while (__any_sync(0xffffffffu, mn < -0.5f)) {
                        mn = 1.0f;
                        #pragma unroll
                        for (int e = 0; e < EDGES; e++) {
                            if (sv[e] == -1.0f) sv[e] = ldg_relaxed(rowp + ssrc_c[e] + lane);
                            mn = fminf(mn, sv[e]);
                        }
                        if (++guard > (1 << 20)) break;   // degrade, never hang
                    }
                }
                #pragma unroll
                for (int e = 0; e < EDGES; e++) scr[e*32 + lane] = sv[e];

                const int par = m & 1;
                const unsigned long long* wp =
                    wf2cell + (size_t)par*(EDGES*WF_Q) + QOFF;
                // e rolled (runtime), q unrolled, ring index m/2+q compile-time
                #pragma unroll 1
                for (int e = 0; e < EDGES; e++) {
                    float s = scr[e*32 + lane];
                    unsigned long long ss = pk2(s, s);
                    const unsigned long long* w = wp + e*WF_Q;
                    #pragma unroll
                    for (int q = 0; q < NP2; q++)
                        fma2(ring[(m >> 1) + q], w[q], ss);
                }
            }
        }
        // export lowest 5 pairs (steps [10v+10, 10v+20)), shift ring by 5, zero top
        const int buf = v & 1;
        #pragma unroll
        for (int q = 0; q < 5; q++) facc[FACC(buf, lc, F, q) + lane] = ring[q];
        #pragma unroll
        for (int p = 0; p < NP-5; p++) ring[p] = ring[p+5];
        #pragma unroll
        for (int p = NP-5; p < NP; p++) ring[p] = 0ull;
        cellbar(barid);
    }
}

// ---------------- the simulation: near/far split, 49 barriers total ----------------
__global__ void __launch_bounds__(TPB, 1)
k_sim(const float* __restrict__ stime,      // (500)
      const float* __restrict__ tcf,        // (600,100)
      const float* __restrict__ fbf,        // (600,100)
      const float* __restrict__ cpf,        // (600,20,100)
      const float* __restrict__ bias,       // (600,1)
      const int*   __restrict__ sel)        // (600,20)
{
    extern __shared__ __align__(16) char dyn[];
    unsigned long long* wn2 = (unsigned long long*)(dyn + OFF_WN2);
    unsigned long long* wf2 = (unsigned long long*)(dyn + OFF_WF2);
    float* swh  = (float*)(dyn + OFF_WHP);
    int*   ssrc = (int*)  (dyn + OFF_SRC);
    float* sstv = (float*)(dyn + OFF_STV);
    unsigned long long* facc = (unsigned long long*)(dyn + OFF_FACC);
    float* sscr = (float*)(dyn + OFF_SCR);

    const int tid = threadIdx.x;
    const int c0 = blockIdx.x * CPC;

    // ---- prologue: near weights wn2[lc][e][10] (pair j = taps d=2j+1, 2j+2; d=1 zeroed) ----
    {
        float2* wn2f = (float2*)wn2;
        for (int i = tid; i < CPC*EDGES*10; i += TPB) {
            int lc = i / (EDGES*10), rem = i % (EDGES*10);
            int e = rem / 10, j = rem % 10;
            int c = c0 + lc;
            const float* f = (e == 0) ? (fbf + (size_t)c*NBF)
                                      : (cpf + ((size_t)c*MC + (e-1))*NBF);
            float a = (j == 0) ? 0.0f : f[99 - 2*j];
            float b = f[98 - 2*j];
            wn2f[i] = make_float2(a, b);
        }
    }
    // ---- far weights wf2[lc][par][e][43]: folders (d0,NT) = (21,26),(47,32),(79,22) ----
    {
        float2* wf2f = (float2*)wf2;
        for (int i = tid; i < CPC*2*EDGES*WF_Q; i += TPB) {
            int lc = i / (2*EDGES*WF_Q), rem = i % (2*EDGES*WF_Q);
            int par = rem / (EDGES*WF_Q), rem2 = rem % (EDGES*WF_Q);
            int e = rem2 / WF_Q, q43 = rem2 % WF_Q;
            int d0, NT, q;
            if      (q43 < 14) { d0 = 21; NT = 26; q = q43;      }
            else if (q43 < 31) { d0 = 47; NT = 32; q = q43 - 14; }
            else               { d0 = 79; NT = 22; q = q43 - 31; }
            int k0 = (par == 0) ? 2*q : 2*q - 1;
            int k1 = k0 + 1;
            int c = c0 + lc;
            const float* f = (e == 0) ? (fbf + (size_t)c*NBF)
                                      : (cpf + ((size_t)c*MC + (e-1))*NBF);
            float a = (k0 >= 0 && k0 < NT) ? f[100 - d0 - k0] : 0.0f;
            float b = (k1 >= 0 && k1 < NT) ? f[100 - d0 - k1] : 0.0f;
            wf2f[i] = make_float2(a, b);
        }
    }
    for (int i = tid; i < CPC*EDGES; i += TPB) {
        int lc = i / EDGES, e = i % EDGES;
        int c = c0 + lc;
        ssrc[lc*EDGES + e] = ((e == 0) ? c : sel[c*MC + (e-1)]) * BATCH;
        swh[lc*EDGES + e]  = (e == 0) ? fbf[(size_t)c*NBF + (NBF-1)]
                                      : cpf[((size_t)c*MC + (e-1))*NBF + (NBF-1)];
    }
    for (int i = tid; i < CPC*NSTEPS; i += TPB) {
        int lc = i / NSTEPS, t = i % NSTEPS;
        int c = c0 + lc;
        float s = 0.f;
        #pragma unroll 4
        for (int f = 0; f < NBF; f++)
            s += __ldg(stime + t + f) * __ldg(tcf + (size_t)c*NBF + f);
        sstv[lc*NSTEPS + t] = s;
    }
    __syncthreads();

    const int wid = tid >> 5, lane = tid & 31;
    const int lc = wid % CPC, r = wid / CPC;     // SMSP-balanced role map
    const int c = c0 + lc;
    const int barid = lc + 1;
    const int myoff = c*BATCH + lane;
    const int* ssrc_c = ssrc + lc*EDGES;

    if (r != 0) {
        // ---------------- FOLDERS ----------------
        const unsigned long long* wf2cell = wf2 + (size_t)lc*(2*EDGES*WF_Q);
        float* scr = sscr + ((lc*3 + (r-1))*EDGES)*32;
        if      (r == 1) run_folder<26, 11, 18, 14,  0, 0>(wf2cell, ssrc_c, facc, scr, lc, lane, barid);
        else if (r == 2) run_folder<32, 37, 21, 17, 14, 1>(wf2cell, ssrc_c, facc, scr, lc, lane, barid);
        else             run_folder<22, 69, 16, 12, 31, 2>(wf2cell, ssrc_c, facc, scr, lc, lane, barid);
        return;
    }

    // ---------------- SEQUENCER ----------------
    const float sapp = g_sapp[myoff];
    const float bv = bias[c];
    const float* stvp = sstv + lc*NSTEPS;
    const float* whp  = swh + lc*EDGES;
    const unsigned long long* wn2p = wn2 + (size_t)lc*(EDGES*10);

    int off[EDGES-1];
    #pragma unroll
    for (int e = 0; e < EDGES-1; e++) off[e] = ssrc_c[e+1] + lane;

    float s_own = g_spk[myoff];          // row 0 (init, always valid)

    unsigned long long accp[NEARP];
    #pragma unroll
    for (int p = 0; p < NEARP; p++) accp[p] = 0ull;

    // prologue prefetch: row 0
    float sv[EDGES];
    #pragma unroll
    for (int e = 1; e < EDGES; e++) sv[e] = ldg_relaxed(g_spk + off[e-1]);

    #pragma unroll 1
    for (int tau = 0; tau < NB; tau++) {
        const float* row = g_spk + (size_t)tau*ROW;
        sv[0] = s_own;

        // validate prefetched gather (row tau), batched re-poll
        if (tau >= NB_INIT) {
            float mn = sv[1];
            #pragma unroll
            for (int e = 2; e < EDGES; e++) mn = fminf(mn, sv[e]);
            int guard = 0;
            while (__any_sync(0xffffffffu, mn < -0.5f)) {
                mn = 1.0f;
                #pragma unroll
                for (int e = 1; e < EDGES; e++) {
                    if (sv[e] == -1.0f) sv[e] = ldg_relaxed(row + off[e-1]);
                    mn = fminf(mn, sv[e]);
                }
                if (++guard > (1 << 20)) break;   // degrade, never hang
            }
        }

        // chunk boundary: barrier, then import far base for steps [tau+1, tau+11)
        if ((tau % 10) == 9 && tau < 10*NV) {
            cellbar(barid);
            const int buf = (tau / 10) & 1;
            #pragma unroll
            for (int q = 0; q < 5; q++) {
                unsigned long long a = facc[FACC(buf, lc, 0, q) + lane];
                unsigned long long b = facc[FACC(buf, lc, 1, q) + lane];
                unsigned long long d = facc[FACC(buf, lc, 2, q) + lane];
                float il = lo2(a) + lo2(b) + lo2(d);
                float ih = hi2(a) + hi2(b) + hi2(d);
                // imported pair q = steps tau+1+2q (pre-shift slot 1+2q = pair q hi)
                //                 and tau+2+2q (slot 2+2q = pair q+1 lo)
                accp[q]   = pk2(lo2(accp[q]),        hi2(accp[q]) + il);
                accp[q+1] = pk2(lo2(accp[q+1]) + ih, hi2(accp[q+1]));
            }
        }

        // PUBLISH-AHEAD: spike(tau+1) complete now (near slot1 + head taps + far base)
        const int tn = tau + 1;
        if (tn < NB) {
            float s;
            if (tn >= NB_INIT) {
                float h = hi2(accp[0]);
                #pragma unroll
                for (int e = 0; e < EDGES; e++) h = fmaf(whp[e], sv[e], h);   // d=1
                float gv = h + sapp * stvp[tn - NB_INIT] + bv;
                s = __fdividef(1.0f, 1.0f + __expf(-gv));
                g_gens[(size_t)(tn - NB_INIT)*ROW + myoff] = gv;
                stg_relaxed(&g_spk[(size_t)tn*ROW + myoff], s);
            } else {
                s = g_spk[(size_t)tn*ROW + myoff];
            }
            s_own = s;
        }

        // shift near ring one slot
        #pragma unroll
        for (int p = 0; p < NEARP-1; p++) accp[p] = pk2(hi2(accp[p]), lo2(accp[p+1]));
        accp[NEARP-1] = pk2(hi2(accp[NEARP-1]), 0.0f);

        // near scatter (d=2..20; d=1 head extracted) + inline prefetch of row tau+1
        const float* nrow = row + ROW;
        #pragma unroll
        for (int e = 0; e < EDGES; e++) {
            unsigned long long ss = pk2(sv[e], sv[e]);
            if (e >= 1) sv[e] = ldg_relaxed(nrow + off[e-1]);
            const unsigned long long* w = wn2p + e*10;
            #pragma unroll
            for (int q = 0; q < NEARP; q++) fma2(accp[q], w[q], ss);
        }
    }
}

// ---------------- output assembly: transpose [t][c][b] -> [b][c][t] ----------------
__global__ void k_out(const float* __restrict__ init, float* __restrict__ out) {
    __shared__ float tile[128][33];
    int c = blockIdx.x, tid = threadIdx.x;
    float* out_s = out;                                      // (32,600,500)
    float* out_g = out + (size_t)BATCH*N_CELLS*NB;           // (32,600,400)

    for (int i = tid; i < BATCH*NB_INIT; i += 128) {
        int b = i / NB_INIT, t = i % NB_INIT;
        out_s[(size_t)b*(N_CELLS*NB) + (size_t)c*NB + t] =
            init[((size_t)b*N_CELLS + c)*NB_INIT + t];
    }
    for (int t0 = NB_INIT; t0 < NB; t0 += 128) {
        int chunk = min(128, NB - t0);
        __syncthreads();
        for (int i = tid; i < chunk*BATCH; i += 128) {
            int tl = i / BATCH, b = i % BATCH;
            tile[tl][b] = g_spk[(size_t)(t0+tl)*ROW + c*BATCH + b];
        }
        __syncthreads();
        for (int i = tid; i < chunk*BATCH; i += 128) {
            int b = i / chunk, tl = i % chunk;
            out_s[(size_t)b*(N_CELLS*NB) + (size_t)c*NB + (t0+tl)] = tile[tl][b];
        }
    }
    for (int t0 = 0; t0 < NSTEPS; t0 += 128) {
        int chunk = min(128, NSTEPS - t0);
        __syncthreads();
        for (int i = tid; i < chunk*BATCH; i += 128) {
            int tl = i / BATCH, b = i % BATCH;
            tile[tl][b] = g_gens[(size_t)(t0+tl)*ROW + c*BATCH + b];
        }
        __syncthreads();
        for (int i = tid; i < chunk*BATCH; i += 128) {
            int b = i / chunk, tl = i % chunk;
            out_g[(size_t)b*(N_CELLS*NSTEPS) + (size_t)c*NSTEPS + (t0+tl)] = tile[tl][b];
        }
    }
}

// ---------------- launch ----------------
extern "C" void kernel_launch(void* const* d_in, const int* in_sizes, int n_in,
                              void* d_out, int out_size) {
    const float* stim  = (const float*)d_in[0];   // (32,64,64)
    const float* init  = (const float*)d_in[1];   // (32,600,100)
    const float* spat  = (const float*)d_in[2];   // (600,64,64)
    const float* tcf   = (const float*)d_in[3];   // (600,100)
    const float* fbf   = (const float*)d_in[4];   // (600,100)
    const float* cpf   = (const float*)d_in[5];   // (600,20,100)
    const float* bias  = (const float*)d_in[6];   // (600,1)
    const int*   sel   = (const int*)d_in[7];     // (600,20)
    const float* stime = (const float*)d_in[8];   // (500,)
    float* out = (float*)d_out;

    cudaFuncSetAttribute(k_sim, cudaFuncAttributeMaxDynamicSharedMemorySize, SMEM_DYN);

    k_stimT<<<BATCH, 256>>>(stim);
    k_sapp<<<N_CELLS, 128>>>(spat);
    k_init<<<(NB*ROW + 255)/256, 256>>>(init);
    k_sim<<<NCTA, TPB, SMEM_DYN>>>(stime, tcf, fbf, cpf, bias, sel);
    k_out<<<N_CELLS, 128>>>(init, out);
}

// round 16
// speedup vs baseline: 1.1999x; 1.1999x over previous
#include <cuda_runtime.h>
#include <cuda_bf16.h>
#include <cstdint>

#define N_CELLS 600
#define HW      4096
#define NBF     100
#define MC      20
#define EDGES   21
#define NB      500
#define NB_INIT 100
#define BATCH   32
#define NSTEPS  400
#define ROW     (N_CELLS*BATCH)   /* 19200 */

// 5 cells per CTA, 4 warps per cell (systolic ring, 28 slots each, 112-slot padded ring)
#define CPC     5
#define WPC     4
#define SLOTS   28
#define NPW     14                 /* f32x2 pairs per warp */
#define NQ      7                  /* float4 loads per edge per warp */
#define RING    112
#define TPB     (CPC*WPC*32)       /* 640 threads */
#define NCTA    (N_CELLS/CPC)      /* 120 CTAs -> 1 per SM, uniform load */

// dynamic smem layout (bytes)
#define OFF_W    0                               /* float[CPC][EDGES][RING] = 47040 */
#define OFF_STV  47040                           /* float[CPC][NSTEPS]      =  8000 */
#define OFF_SRC  55040                           /* int  [CPC][EDGES]  (pad 448)    */
#define OFF_WH   55488                           /* float[CPC][EDGES]  (pad 448)    */
#define OFF_SPK  55936                           /* float[2][CPC][32]       =  1280 */
#define OFF_BND  57216                           /* float[2][CPC][WPC][32]  =  5120 */
#define SMEM_DYN 62336

// ---------------- scratch: __device__ globals (no allocations allowed) ----------------
// +1 pad row: the inline prefetch at tau=NB-1 reads row NB (never used, never canary-polled)
__device__ float g_spk [(NB+1) * N_CELLS * BATCH];  // [t][c][b], canary -1 until written
__device__ float g_gens[NSTEPS * N_CELLS * BATCH];  // [t'][c][b]
__device__ float g_stimT[HW * BATCH];               // [hw][b]
__device__ float g_sapp [N_CELLS * BATCH];          // [c][b]

// ---------------- helpers ----------------
__device__ __forceinline__ float ldg_relaxed(const float* p) {
    float v;
    asm volatile("ld.relaxed.gpu.global.f32 %0, [%1];" : "=f"(v) : "l"(p));
    return v;
}
__device__ __forceinline__ void stg_relaxed(float* p, float v) {
    asm volatile("st.relaxed.gpu.global.f32 [%0], %1;" :: "l"(p), "f"(v) : "memory");
}
__device__ __forceinline__ unsigned long long pk2(float lo, float hi) {
    unsigned long long u;
    asm("mov.b64 %0, {%1, %2};" : "=l"(u) : "f"(lo), "f"(hi));
    return u;
}
__device__ __forceinline__ float lo2(unsigned long long u) {
    float a, b;
    asm("mov.b64 {%0, %1}, %2;" : "=f"(a), "=f"(b) : "l"(u));
    return a;
}
__device__ __forceinline__ float hi2(unsigned long long u) {
    float a, b;
    asm("mov.b64 {%0, %1}, %2;" : "=f"(a), "=f"(b) : "l"(u));
    return b;
}
__device__ __forceinline__ void fma2(unsigned long long& acc, unsigned long long w, unsigned long long s) {
    asm("fma.rn.f32x2 %0, %1, %2, %0;" : "+l"(acc) : "l"(w), "l"(s));
}
__device__ __forceinline__ void cellbar(int id) {
    asm volatile("bar.sync %0, %1;" :: "r"(id), "r"(WPC*32) : "memory");
}

// ---------------- setup: transpose stimulus to [hw][b] ----------------
__global__ void k_stimT(const float* __restrict__ stim) {
    int b = blockIdx.x;
    for (int i = threadIdx.x; i < HW; i += blockDim.x)
        g_stimT[i*BATCH + b] = stim[(size_t)b*HW + i];
}

// ---------------- setup: stim_applied[c][b] = stim_flat[b] . spat_flat[c] ----------------
__global__ void k_sapp(const float* __restrict__ spat) {
    __shared__ float red[128];
    int c = blockIdx.x;
    int tid = threadIdx.x;
    int g = tid >> 5, b = tid & 31;
    float acc = 0.f;
    const float* sp = spat + (size_t)c*HW;
    #pragma unroll 8
    for (int m = 0; m < HW/4; m++) {
        int i = g + 4*m;
        acc += sp[i] * g_stimT[i*BATCH + b];
    }
    red[tid] = acc;
    __syncthreads();
    if (tid < 32)
        g_sapp[c*BATCH + tid] = red[tid] + red[tid+32] + red[tid+64] + red[tid+96];
}

// ---------------- setup: initial spikes transposed + canary fill ----------------
__global__ void k_init(const float* __restrict__ init) {
    int idx = blockIdx.x*blockDim.x + threadIdx.x;
    if (idx >= NB*ROW) return;
    int tau = idx / ROW, r = idx % ROW;
    int cc = r / BATCH, b = r % BATCH;
    g_spk[idx] = (tau < NB_INIT) ? init[((size_t)b*N_CELLS + cc)*NB_INIT + tau] : -1.0f;
}

// ---------------- simulation: publisher-priority publish-ahead systolic ring ----------
__global__ void __launch_bounds__(TPB, 1)
k_sim(const float* __restrict__ stime,      // (500)
      const float* __restrict__ tcf,        // (600,100)
      const float* __restrict__ fbf,        // (600,100)
      const float* __restrict__ cpf,        // (600,20,100)
      const float* __restrict__ bias,       // (600,1)
      const int*   __restrict__ sel)        // (600,20)
{
    extern __shared__ __align__(16) char dyn[];
    float* sw   = (float*)(dyn + OFF_W);     // [lc][e][j] tap-reversed; j==0 ZEROED (head extracted)
    float* sstv = (float*)(dyn + OFF_STV);   // [lc][t]
    int*   ssrc = (int*)  (dyn + OFF_SRC);   // [lc][e] = src*BATCH
    float* swh  = (float*)(dyn + OFF_WH);    // [lc][e] head tap weight w_rev[0] = filter[99]
    float* sspk = (float*)(dyn + OFF_SPK);   // [par][lc][32] self-spike stash
    float* sbnd = (float*)(dyn + OFF_BND);   // [par][lc][r][32] boundary export

    const int tid = threadIdx.x;
    const int c0 = blockIdx.x * CPC;

    // ---- prologue ----
    for (int i = tid; i < CPC*EDGES*RING; i += TPB) {
        int lc = i / (EDGES*RING), rr = i % (EDGES*RING);
        int e = rr / RING, j = rr % RING;
        int c = c0 + lc;
        float v = 0.0f;
        if (j >= 1 && j < NBF)                 // j==0 is the head tap: lives in swh instead
            v = (e == 0) ? fbf[(size_t)c*NBF + (NBF-1-j)]
                         : cpf[((size_t)c*MC + (e-1))*NBF + (NBF-1-j)];
        sw[i] = v;
    }
    for (int i = tid; i < CPC*EDGES; i += TPB) {
        int lc = i / EDGES, e = i % EDGES;
        int c = c0 + lc;
        ssrc[i] = ((e == 0) ? c : sel[c*MC + (e-1)]) * BATCH;
        swh[i]  = (e == 0) ? fbf[(size_t)c*NBF + (NBF-1)]
                           : cpf[((size_t)c*MC + (e-1))*NBF + (NBF-1)];
    }
    for (int i = tid; i < CPC*NSTEPS; i += TPB) {
        int lc = i / NSTEPS, t = i % NSTEPS;
        int c = c0 + lc;
        float s = 0.f;
        #pragma unroll 4
        for (int f = 0; f < NBF; f++)
            s += __ldg(stime + t + f) * __ldg(tcf + (size_t)c*NBF + f);
        sstv[i] = s;
    }
    __syncthreads();

    const int wid = tid >> 5, lane = tid & 31;
    // PUBLISHER-PRIORITY MAP: r = WPC-1 - wid/CPC, lc = wid % CPC.
    // B300 arbiter is highest-wid-first. Publishers (r==0) = wids 15..19, the
    // HIGHEST-priority warp on each SMSP -> the global critical chain
    // (validate -> publish -> store) never queues behind scatter bursts.
    const int lc = wid % CPC, r = (WPC-1) - (wid / CPC);
    const int c = c0 + lc;
    const int barid = lc + 1;
    const int myoff = c*BATCH + lane;
    const float sapp = g_sapp[myoff];
    const float bv = bias[c];
    const float* wbase = sw + lc*(EDGES*RING) + r*SLOTS;
    const float* stvp  = sstv + lc*NSTEPS;
    const float* whp   = swh + lc*EDGES;

    int off[EDGES-1];
    #pragma unroll
    for (int e = 0; e < EDGES-1; e++) off[e] = ssrc[lc*EDGES + e + 1] + lane;

    // prologue stash: self spike for tau=0 (parity 0)
    if (r == 0) sspk[0*CPC*32 + lc*32 + lane] = g_spk[myoff];

    unsigned long long accp[NPW];
    #pragma unroll
    for (int p = 0; p < NPW; p++) accp[p] = 0ull;
    __syncthreads();

    // ---- prologue prefetch: gather row 0 (init-written, always valid) ----
    float sv[EDGES];
    #pragma unroll
    for (int e = 1; e < EDGES; e++) sv[e] = ldg_relaxed(g_spk + off[e-1]);

    #pragma unroll 2
    for (int tau = 0; tau < NB; tau++) {
        const int par = tau & 1;
        const float* row = g_spk + (size_t)tau*ROW;

        // ---- validate prefetched gather (sv holds row tau, loaded last body) ----
        sv[0] = sspk[par*CPC*32 + lc*32 + lane];            // stashed last iter
        if (tau >= NB_INIT) {
            float mn = sv[1];
            #pragma unroll
            for (int e = 2; e < EDGES; e++) mn = fminf(mn, sv[e]);
            if (__any_sync(0xffffffffu, mn < -0.5f)) {
                #pragma unroll
                for (int e = 1; e < EDGES; e++) {
                    int guard = 0;
                    while (__any_sync(0xffffffffu, sv[e] == -1.0f)) {
                        sv[e] = ldg_relaxed(row + off[e-1]);
                        if (++guard > (1 << 22)) break;   // degrade, never hang
                    }
                }
            }
        }

        // ---- PUBLISH-AHEAD: spike(tau+1) is complete right now; push it out early ----
        if (r == 0) {
            const int tn = tau + 1;
            if (tn < NB) {
                float s;
                if (tn >= NB_INIT) {
                    float h = hi2(accp[0]);               // slot1 pre-shift: taps f=1..98 done
                    #pragma unroll
                    for (int e = 0; e < EDGES; e++) h = fmaf(whp[e], sv[e], h);  // tap f=99
                    int t = tn - NB_INIT;
                    float gv = h + sapp * stvp[t] + bv;
                    s = __fdividef(1.0f, 1.0f + __expf(-gv));
                    g_gens[(size_t)t*ROW + myoff] = gv;
                    stg_relaxed(&g_spk[(size_t)tn*ROW + myoff], s);
                } else {
                    s = g_spk[(size_t)tn*ROW + myoff];    // prefetch init spike
                }
                sspk[(par^1)*CPC*32 + lc*32 + lane] = s;  // stash for next iter
            }
        } else {
            sbnd[par*CPC*WPC*32 + (lc*WPC + r)*32 + lane] = lo2(accp[0]);  // boundary export
        }
        cellbar(barid);

        // ---- shift segment down one slot; import neighbor's head (or 0 at tail) ----
        float incoming = (r < WPC-1)
            ? sbnd[par*CPC*WPC*32 + (lc*WPC + r + 1)*32 + lane] : 0.0f;
        #pragma unroll
        for (int p = 0; p < NPW-1; p++) accp[p] = pk2(hi2(accp[p]), lo2(accp[p+1]));
        accp[NPW-1] = pk2(hi2(accp[NPW-1]), incoming);

        // ---- bulk scatter with inline prefetch of row tau+1 (register-neutral) ----
        const float* nrow = row + ROW;
        #pragma unroll
        for (int e = 0; e < EDGES; e++) {
            unsigned long long ss = pk2(sv[e], sv[e]);
            if (e >= 1) sv[e] = ldg_relaxed(nrow + off[e-1]);   // prefetch next row
            const float4* wp = (const float4*)(wbase + e*RING);
            #pragma unroll
            for (int q = 0; q < NQ; q++) {
                float4 w4 = wp[q];
                fma2(accp[2*q],   pk2(w4.x, w4.y), ss);
                fma2(accp[2*q+1], pk2(w4.z, w4.w), ss);
            }
        }
    }
}

// ---------------- output assembly: transpose [t][c][b] -> [b][c][t] ----------------
__global__ void k_out(const float* __restrict__ init, float* __restrict__ out) {
    __shared__ float tile[128][33];
    int c = blockIdx.x, tid = threadIdx.x;
    float* out_s = out;                                      // (32,600,500)
    float* out_g = out + (size_t)BATCH*N_CELLS*NB;           // (32,600,400)

    for (int i = tid; i < BATCH*NB_INIT; i += 128) {
        int b = i / NB_INIT, t = i % NB_INIT;
        out_s[(size_t)b*(N_CELLS*NB) + (size_t)c*NB + t] =
            init[((size_t)b*N_CELLS + c)*NB_INIT + t];
    }
    for (int t0 = NB_INIT; t0 < NB; t0 += 128) {
        int chunk = min(128, NB - t0);
        __syncthreads();
        for (int i = tid; i < chunk*BATCH; i += 128) {
            int tl = i / BATCH, b = i % BATCH;
            tile[tl][b] = g_spk[(size_t)(t0+tl)*ROW + c*BATCH + b];
        }
        __syncthreads();
        for (int i = tid; i < chunk*BATCH; i += 128) {
            int b = i / chunk, tl = i % chunk;
            out_s[(size_t)b*(N_CELLS*NB) + (size_t)c*NB + (t0+tl)] = tile[tl][b];
        }
    }
    for (int t0 = 0; t0 < NSTEPS; t0 += 128) {
        int chunk = min(128, NSTEPS - t0);
        __syncthreads();
        for (int i = tid; i < chunk*BATCH; i += 128) {
            int tl = i / BATCH, b = i % BATCH;
            tile[tl][b] = g_gens[(size_t)(t0+tl)*ROW + c*BATCH + b];
        }
        __syncthreads();
        for (int i = tid; i < chunk*BATCH; i += 128) {
            int b = i / chunk, tl = i % chunk;
            out_g[(size_t)b*(N_CELLS*NSTEPS) + (size_t)c*NSTEPS + (t0+tl)] = tile[tl][b];
        }
    }
}

// ---------------- launch ----------------
extern "C" void kernel_launch(void* const* d_in, const int* in_sizes, int n_in,
                              void* d_out, int out_size) {
    const float* stim  = (const float*)d_in[0];   // (32,64,64)
    const float* init  = (const float*)d_in[1];   // (32,600,100)
    const float* spat  = (const float*)d_in[2];   // (600,64,64)
    const float* tcf   = (const float*)d_in[3];   // (600,100)
    const float* fbf   = (const float*)d_in[4];   // (600,100)
    const float* cpf   = (const float*)d_in[5];   // (600,20,100)
    const float* bias  = (const float*)d_in[6];   // (600,1)
    const int*   sel   = (const int*)d_in[7];     // (600,20)
    const float* stime = (const float*)d_in[8];   // (500,)
    float* out = (float*)d_out;

    cudaFuncSetAttribute(k_sim, cudaFuncAttributeMaxDynamicSharedMemorySize, SMEM_DYN);

    k_stimT<<<BATCH, 256>>>(stim);
    k_sapp<<<N_CELLS, 128>>>(spat);
    k_init<<<(NB*ROW + 255)/256, 256>>>(init);
    k_sim<<<NCTA, TPB, SMEM_DYN>>>(stime, tcf, fbf, cpf, bias, sel);
    k_out<<<N_CELLS, 128>>>(init, out);
}